// round 14
// baseline (speedup 1.0000x reference)
#include <cuda_runtime.h>
#include <cstdint>
#include <algorithm>

// ---------------------------------------------------------------------------
// Problem constants
// ---------------------------------------------------------------------------
#define BATCH   256
#define FDIM    128
#define EDIM    128
#define DDIM    64
#define MAXDEG  64
#define NN1     25
#define NN0     10
#define ROWS1   (BATCH * 2 * NN1)     // 12800 per set
#define ROWS_BIG (2 * ROWS1)          // 25600
#define KDIM    384

#define RPB     64                    // rows per block in fused_l0
#define ASTRIDE 388                   // 384 + 4 pad -> conflict-free A-frag LDS
#define SM_A    (RPB * ASTRIDE)       // 24832 floats
#define BSZ     (8 * 128)             // one hi 8-k panel (1024 floats)
#define SM_B    (2 * BSZ)             // double-buffered hi panels
#define SMEM_FUSED ((SM_A + SM_B) * 4)   // 107520 B (2 blocks/SM)

#define L0_BLOCKS (ROWS_BIG / RPB)    // 400
#define S1_BLOCKS 64
#define PREP_BLOCKS (KDIM * EDIM / 256)   // 192
#define B1_BLOCKS ((2 * ROWS1 + 255) / 256) // 100

// ---------------------------------------------------------------------------
// Static device scratch
// ---------------------------------------------------------------------------
__device__ int   g_lvl1[2][ROWS1];
__device__ float g_h11[(size_t)ROWS_BIG * EDIM];      // 13.1 MB
__device__ float g_h10[2 * BATCH * EDIM];
__device__ float g_Whi[KDIM * EDIM];

struct ColsAll {
    int out0[2][NN1];
    int in0[2][NN1];
    int out1[2][NN0];
    int in1[2][NN0];
};

// ---------------------------------------------------------------------------
// Helpers
// ---------------------------------------------------------------------------
__device__ __forceinline__ float sigmoidf_stable(float x) {
    if (x >= 0.f) {
        return 1.f / (1.f + expf(-x));
    } else {
        float e = expf(x);
        return e / (1.f + e);
    }
}

__device__ __forceinline__ unsigned tf32_rna(float x) {
    unsigned r;
    asm("cvt.rna.tf32.f32 %0, %1;" : "=r"(r) : "f"(x));
    return r;
}

__device__ __forceinline__ void mma_tf32(float* c,
                                         unsigned a0, unsigned a1,
                                         unsigned a2, unsigned a3,
                                         unsigned b0, unsigned b1) {
    asm volatile(
        "mma.sync.aligned.m16n8k8.row.col.f32.tf32.tf32.f32 "
        "{%0,%1,%2,%3}, {%4,%5,%6,%7}, {%8,%9}, {%0,%1,%2,%3};"
        : "+f"(c[0]), "+f"(c[1]), "+f"(c[2]), "+f"(c[3])
        : "r"(a0), "r"(a1), "r"(a2), "r"(a3), "r"(b0), "r"(b1));
}

// ---------------------------------------------------------------------------
// #1: build_lvl1 + prep_w combined
// ---------------------------------------------------------------------------
__global__ void comb_b1_prep(const int* __restrict__ nodes1,
                             const int* __restrict__ nodes2,
                             const int* __restrict__ nbr_out,
                             const int* __restrict__ nbr_in,
                             const float* __restrict__ W,
                             ColsAll cols) {
    if (blockIdx.x < PREP_BLOCKS) {
        int idx = blockIdx.x * 256 + threadIdx.x;
        g_Whi[idx] = __uint_as_float(tf32_rna(W[idx]));
        return;
    }
    int tid = (blockIdx.x - PREP_BLOCKS) * 256 + threadIdx.x;
    const int total = 2 * ROWS1;
    if (tid >= total) return;
    int set = tid / ROWS1;
    int rem = tid - set * ROWS1;
    int i = rem / (2 * NN1);
    int j = rem - i * (2 * NN1);
    int node = (set ? nodes2 : nodes1)[i];
    int col;
    const int* nbr;
    if (j < NN1) { col = cols.out0[set][j];        nbr = nbr_out; }
    else         { col = cols.in0[set][j - NN1];   nbr = nbr_in;  }
    g_lvl1[set][rem] = nbr[(size_t)node * MAXDEG + col];
}

// ---------------------------------------------------------------------------
// #2: fused_l0 (blocks 0..399, inline level-2 indices) + fused_s1 (400..463)
// ---------------------------------------------------------------------------
__global__ void __launch_bounds__(256, 2)
fused_l0s1(const float* __restrict__ feat,
           const int* __restrict__ nodes1,
           const int* __restrict__ nodes2,
           const int* __restrict__ nbr_out,
           const int* __restrict__ nbr_in,
           const float* __restrict__ W,
           ColsAll cols) {
    extern __shared__ float sm[];
    const int t    = threadIdx.x;
    const int lane = t & 31;
    const int w    = t >> 5;

    const float4* feat4 = reinterpret_cast<const float4*>(feat);

    if (blockIdx.x >= L0_BLOCKS) {
        // ================== fused_s1 path ==================
        float* As = sm;                       // [8][ASTRIDE]
        float* Bs = sm + 8 * ASTRIDE;         // [16][128]
        const int b = blockIdx.x - L0_BLOCKS; // 0..63

        {   // gather: warp w -> row w
            int R = b * 8 + w;                // 0..511
            int set = R >> 8, i = R & 255;
            int self = (set ? nodes2 : nodes1)[i];
            const int* l1 = &g_lvl1[set][i * 2 * NN1];
            const float inv = 1.0f / (float)NN1;

            float4 vs = feat4[(size_t)self * 32 + lane];
            float4 ao = make_float4(0.f, 0.f, 0.f, 0.f);
            float4 ai = make_float4(0.f, 0.f, 0.f, 0.f);
#pragma unroll
            for (int j = 0; j < NN1; j++) {
                float4 v = feat4[(size_t)l1[j] * 32 + lane];
                ao.x += v.x; ao.y += v.y; ao.z += v.z; ao.w += v.w;
            }
#pragma unroll
            for (int j = NN1; j < 2 * NN1; j++) {
                float4 v = feat4[(size_t)l1[j] * 32 + lane];
                ai.x += v.x; ai.y += v.y; ai.z += v.z; ai.w += v.w;
            }
            float* arow = &As[w * ASTRIDE];
            *reinterpret_cast<float4*>(&arow[lane * 4]) = vs;
            *reinterpret_cast<float4*>(&arow[128 + lane * 4]) =
                make_float4(ao.x * inv, ao.y * inv, ao.z * inv, ao.w * inv);
            *reinterpret_cast<float4*>(&arow[256 + lane * 4]) =
                make_float4(ai.x * inv, ai.y * inv, ai.z * inv, ai.w * inv);
        }
        __syncthreads();

        const int tx = t & 31;
        float acc[4] = {0.f, 0.f, 0.f, 0.f};
        for (int k0 = 0; k0 < KDIM; k0 += 16) {
#pragma unroll
            for (int l = 0; l < 2; l++) {
                int f4 = t * 2 + l;
                int k  = f4 >> 5;
                int c  = (f4 & 31) * 4;
                *reinterpret_cast<float4*>(&Bs[k * 128 + c]) =
                    *reinterpret_cast<const float4*>(&W[(size_t)(k0 + k) * EDIM + c]);
            }
            __syncthreads();
#pragma unroll
            for (int k = 0; k < 16; k++) {
                float4 bv = *reinterpret_cast<const float4*>(&Bs[k * 128 + tx * 4]);
                float a = As[w * ASTRIDE + k0 + k];
                acc[0] += a * bv.x; acc[1] += a * bv.y;
                acc[2] += a * bv.z; acc[3] += a * bv.w;
            }
            __syncthreads();
        }
        int R = b * 8 + w;
        float4 o;
        o.x = sigmoidf_stable(acc[0]);
        o.y = sigmoidf_stable(acc[1]);
        o.z = sigmoidf_stable(acc[2]);
        o.w = sigmoidf_stable(acc[3]);
        *reinterpret_cast<float4*>(&g_h10[(size_t)R * EDIM + tx * 4]) = o;
        return;
    }

    // ================== fused_l0 path ==================
    float* As = sm;                 // [RPB][ASTRIDE]
    float* Bs = sm + SM_A;          // phase 2: B panels; phase 1: idx scratch
    int*   idxsm = reinterpret_cast<int*>(Bs);   // [8 warps][8 rows][20]
    const int r0 = blockIdx.x * RPB;
    const int set = (r0 >= ROWS1) ? 1 : 0;       // whole block same set
    const int i0 = r0 - set * ROWS1;

    // ---- Phase 1a: compute level-2 indices inline ----
    {
        int parents[8];
#pragma unroll
        for (int rr = 0; rr < 8; rr++) {
            int i = i0 + w * 8 + rr;
            parents[rr] = g_lvl1[set][i];
        }
        if (lane < 2 * NN0) {
            int col = (lane < NN0) ? cols.out1[set][lane]
                                   : cols.in1[set][lane - NN0];
            const int* nbr = (lane < NN0) ? nbr_out : nbr_in;
#pragma unroll
            for (int rr = 0; rr < 8; rr++) {
                idxsm[(w * 8 + rr) * 20 + lane] =
                    nbr[(size_t)parents[rr] * MAXDEG + col];
            }
        }
        __syncwarp();

        // ---- Phase 1b: gather + mean into smem A ----
        const float inv = 1.0f / (float)NN0;
#pragma unroll
        for (int rr = 0; rr < 8; rr++) {
            int r = w * 8 + rr;
            const int* l2 = &idxsm[r * 20];

            float4 vs = feat4[(size_t)parents[rr] * 32 + lane];
            float4 ao = make_float4(0.f, 0.f, 0.f, 0.f);
            float4 ai = make_float4(0.f, 0.f, 0.f, 0.f);
#pragma unroll
            for (int j = 0; j < NN0; j++) {
                float4 v = feat4[(size_t)l2[j] * 32 + lane];
                ao.x += v.x; ao.y += v.y; ao.z += v.z; ao.w += v.w;
            }
#pragma unroll
            for (int j = NN0; j < 2 * NN0; j++) {
                float4 v = feat4[(size_t)l2[j] * 32 + lane];
                ai.x += v.x; ai.y += v.y; ai.z += v.z; ai.w += v.w;
            }
            float* arow = &As[r * ASTRIDE];
            *reinterpret_cast<float4*>(&arow[lane * 4]) = vs;
            *reinterpret_cast<float4*>(&arow[128 + lane * 4]) =
                make_float4(ao.x * inv, ao.y * inv, ao.z * inv, ao.w * inv);
            *reinterpret_cast<float4*>(&arow[256 + lane * 4]) =
                make_float4(ai.x * inv, ai.y * inv, ai.z * inv, ai.w * inv);
        }
    }

    // ---- Phase 2: 2-term TF32 MMA, double-buffered B, pipelined A frags ----
    const int group = lane >> 2;
    const int tid4  = lane & 3;
    const int R0w   = (w & 3) * 16;
    const int C0    = (w >> 2) * 64;

    float acc[8][4];
#pragma unroll
    for (int j = 0; j < 8; j++)
#pragma unroll
        for (int q = 0; q < 4; q++) acc[j][q] = 0.f;

    const int pk = t >> 5;
    const int pn = (t & 31) * 4;
    const int sb = pk * 128 + (pn ^ (pk * 8));

    const int ob0 = tid4 * 128;
    const int ob1 = (tid4 + 4) * 128;
    const int xr0 = tid4 * 8;
    const int xr1 = (tid4 + 4) * 8;

    const float* arb  = &As[(R0w + group) * ASTRIDE];
    const float* arb8 = arb + 8 * ASTRIDE;

    float4 whi = *reinterpret_cast<const float4*>(&g_Whi[pk * EDIM + pn]);
    __syncthreads();   // As complete, idx scratch dead

    float x00 = arb[tid4];
    float x10 = arb8[tid4];
    float x01 = arb[tid4 + 4];
    float x11 = arb8[tid4 + 4];

    *reinterpret_cast<float4*>(&Bs[sb]) = whi;                   // panel 0 -> buf 0
    whi = *reinterpret_cast<const float4*>(&g_Whi[(8 + pk) * EDIM + pn]);
    __syncthreads();   // buf 0 visible

    const int NP = KDIM / 8;   // 48
    for (int p = 0; p < NP; p++) {
        const float* buf = &Bs[(p & 1) * BSZ];

        if (p + 1 < NP) {
            *reinterpret_cast<float4*>(&Bs[((p + 1) & 1) * BSZ + sb]) = whi;
            if (p + 2 < NP) {
                whi = *reinterpret_cast<const float4*>(
                    &g_Whi[((p + 2) * 8 + pk) * EDIM + pn]);
            }
        }

        unsigned ah0 = tf32_rna(x00), ah1 = tf32_rna(x10),
                 ah2 = tf32_rna(x01), ah3 = tf32_rna(x11);
        unsigned al0 = tf32_rna(x00 - __uint_as_float(ah0));
        unsigned al1 = tf32_rna(x10 - __uint_as_float(ah1));
        unsigned al2 = tf32_rna(x01 - __uint_as_float(ah2));
        unsigned al3 = tf32_rna(x11 - __uint_as_float(ah3));

        if (p + 1 < NP) {
            int ko = (p + 1) * 8;
            x00 = arb[ko + tid4];
            x10 = arb8[ko + tid4];
            x01 = arb[ko + tid4 + 4];
            x11 = arb8[ko + tid4 + 4];
        }

#pragma unroll
        for (int j = 0; j < 8; j++) {
            int nl = C0 + j * 8 + group;
            unsigned bh0 = __float_as_uint(buf[ob0 + (nl ^ xr0)]);
            unsigned bh1 = __float_as_uint(buf[ob1 + (nl ^ xr1)]);
            mma_tf32(acc[j], ah0, ah1, ah2, ah3, bh0, bh1);
            mma_tf32(acc[j], al0, al1, al2, al3, bh0, bh1);
        }
        __syncthreads();
    }

    // ---- Epilogue: sigmoid + store ----
    const int Ra = r0 + R0w + group;
    const int Rb = Ra + 8;
#pragma unroll
    for (int j = 0; j < 8; j++) {
        int col = C0 + j * 8 + 2 * tid4;
        float2 oa, ob;
        oa.x = sigmoidf_stable(acc[j][0]);
        oa.y = sigmoidf_stable(acc[j][1]);
        ob.x = sigmoidf_stable(acc[j][2]);
        ob.y = sigmoidf_stable(acc[j][3]);
        *reinterpret_cast<float2*>(&g_h11[(size_t)Ra * EDIM + col]) = oa;
        *reinterpret_cast<float2*>(&g_h11[(size_t)Rb * EDIM + col]) = ob;
    }
}

// ---------------------------------------------------------------------------
// #3: fused_s2: layer-1 agg ONCE + 3 heads (GEMM+sigmoid+proj) -> out
// Grid 64, block 256; 8 rows per block.
// ---------------------------------------------------------------------------
__global__ void __launch_bounds__(256)
fused_s2(const float* __restrict__ Wm, const float* __restrict__ Ws,
         const float* __restrict__ Wp,
         const float* __restrict__ Wdm, const float* __restrict__ Wds,
         const float* __restrict__ Wdp,
         float* __restrict__ out) {
    __shared__ float As[8 * ASTRIDE];
    __shared__ float Bs[16 * 128];
    __shared__ float Hs[8 * 132];

    const int t = threadIdx.x, lane = t & 31, w = t >> 5;

    // ---- layer-1 aggregation ONCE (warp w -> row w) ----
    {
        int R = blockIdx.x * 8 + w;
        int set = R >> 8, i = R & 255;
        const float4* h4 = reinterpret_cast<const float4*>(
            &g_h11[(size_t)(set * ROWS1 + i * 2 * NN1) * EDIM]);
        const float inv = 1.0f / (float)NN1;

        float4 vs = reinterpret_cast<const float4*>(&g_h10[(size_t)R * EDIM])[lane];
        float4 ao = make_float4(0.f, 0.f, 0.f, 0.f);
        float4 ai = make_float4(0.f, 0.f, 0.f, 0.f);
#pragma unroll
        for (int j = 0; j < NN1; j++) {
            float4 v = h4[(size_t)j * 32 + lane];
            ao.x += v.x; ao.y += v.y; ao.z += v.z; ao.w += v.w;
        }
#pragma unroll
        for (int j = NN1; j < 2 * NN1; j++) {
            float4 v = h4[(size_t)j * 32 + lane];
            ai.x += v.x; ai.y += v.y; ai.z += v.z; ai.w += v.w;
        }
        float* arow = &As[w * ASTRIDE];
        *reinterpret_cast<float4*>(&arow[lane * 4]) = vs;
        *reinterpret_cast<float4*>(&arow[128 + lane * 4]) =
            make_float4(ao.x * inv, ao.y * inv, ao.z * inv, ao.w * inv);
        *reinterpret_cast<float4*>(&arow[256 + lane * 4]) =
            make_float4(ai.x * inv, ai.y * inv, ai.z * inv, ai.w * inv);
    }
    __syncthreads();

    const int tx = t & 31;

    for (int head = 0; head < 3; head++) {
        const float* W  = (head == 0) ? Wm  : (head == 1) ? Ws  : Wp;
        const float* Wd = (head == 0) ? Wdm : (head == 1) ? Wds : Wdp;

        // ---- head GEMM + sigmoid -> Hs ----
        float acc[4] = {0.f, 0.f, 0.f, 0.f};
        for (int k0 = 0; k0 < KDIM; k0 += 16) {
#pragma unroll
            for (int l = 0; l < 2; l++) {
                int f4 = t * 2 + l;
                int k  = f4 >> 5;
                int c  = (f4 & 31) * 4;
                *reinterpret_cast<float4*>(&Bs[k * 128 + c]) =
                    *reinterpret_cast<const float4*>(&W[(size_t)(k0 + k) * EDIM + c]);
            }
            __syncthreads();
#pragma unroll
            for (int k = 0; k < 16; k++) {
                float4 b = *reinterpret_cast<const float4*>(&Bs[k * 128 + tx * 4]);
                float a = As[w * ASTRIDE + k0 + k];
                acc[0] += a * b.x; acc[1] += a * b.y;
                acc[2] += a * b.z; acc[3] += a * b.w;
            }
            __syncthreads();
        }

        {
            float4 o;
            o.x = sigmoidf_stable(acc[0]);
            o.y = sigmoidf_stable(acc[1]);
            o.z = sigmoidf_stable(acc[2]);
            o.w = sigmoidf_stable(acc[3]);
            *reinterpret_cast<float4*>(&Hs[w * 132 + tx * 4]) = o;
        }
        __syncthreads();

        // ---- projection: z[8][64] = Hs[8][128] @ Wd[128][64] ----
        {
            int r  = t >> 5;
            int cg = t & 31;
            float s0 = 0.f, s1 = 0.f;
#pragma unroll
            for (int k = 0; k < 128; k++) {
                float hv = Hs[r * 132 + k];
                float2 wd = *reinterpret_cast<const float2*>(&Wd[k * DDIM + cg * 2]);
                s0 += hv * wd.x;
                s1 += hv * wd.y;
            }
            int R = blockIdx.x * 8 + r;
            int set = R >> 8, i = R & 255;
            float2 z = make_float2(s0, s1);
            *reinterpret_cast<float2*>(
                &out[((size_t)(set * 3 + head) * BATCH + i) * DDIM + cg * 2]) = z;
        }
        __syncthreads();   // Hs/Bs reuse by next head
    }
}

// ---------------------------------------------------------------------------
// Host-side JAX threefry reproduction (partitionable mode)
// ---------------------------------------------------------------------------
namespace tfry {

static inline uint32_t rotl32(uint32_t x, int d) { return (x << d) | (x >> (32 - d)); }

struct Key { uint32_t a, b; };

static Key threefry2x32(Key k, uint32_t x0, uint32_t x1) {
    uint32_t ks0 = k.a, ks1 = k.b, ks2 = k.a ^ k.b ^ 0x1BD11BDAu;
    x0 += ks0; x1 += ks1;
    static const int R0[4] = {13, 15, 26, 6};
    static const int R1[4] = {17, 29, 16, 24};
    auto rounds4 = [&](const int* R) {
        for (int i = 0; i < 4; i++) { x0 += x1; x1 = rotl32(x1, R[i]); x1 ^= x0; }
    };
    rounds4(R0); x0 += ks1; x1 += ks2 + 1u;
    rounds4(R1); x0 += ks2; x1 += ks0 + 2u;
    rounds4(R0); x0 += ks0; x1 += ks1 + 3u;
    rounds4(R1); x0 += ks1; x1 += ks2 + 4u;
    rounds4(R0); x0 += ks2; x1 += ks0 + 5u;
    return Key{x0, x1};
}

static Key fold(Key k, uint32_t i) { return threefry2x32(k, 0u, i); }

static void perm64_prefix(Key key, int n, int* out) {
    Key subkey = fold(key, 1);
    uint32_t bits[64];
    int idx[64];
    for (int i = 0; i < 64; i++) {
        Key r = threefry2x32(subkey, 0u, (uint32_t)i);
        bits[i] = r.a ^ r.b;
        idx[i] = i;
    }
    std::stable_sort(idx, idx + 64,
                     [&](int x, int y) { return bits[x] < bits[y]; });
    for (int j = 0; j < n; j++) out[j] = idx[j];
}

}  // namespace tfry

// ---------------------------------------------------------------------------
// kernel_launch
// ---------------------------------------------------------------------------
extern "C" void kernel_launch(void* const* d_in, const int* in_sizes, int n_in,
                              void* d_out, int out_size) {
    const int*   nodes1  = (const int*)d_in[0];
    const int*   nodes2  = (const int*)d_in[1];
    const int*   nbr_out = (const int*)d_in[2];
    const int*   nbr_in  = (const int*)d_in[3];
    const float* feat    = (const float*)d_in[4];
    const float* W_in    = (const float*)d_in[5];
    const float* W_mean  = (const float*)d_in[6];
    const float* W_std   = (const float*)d_in[7];
    const float* W_pi    = (const float*)d_in[8];
    const float* Wd_mean = (const float*)d_in[11];
    const float* Wd_std  = (const float*)d_in[12];
    const float* Wd_pi   = (const float*)d_in[13];
    float* out = (float*)d_out;

    cudaFuncSetAttribute(fused_l0s1, cudaFuncAttributeMaxDynamicSharedMemorySize,
                         SMEM_FUSED);

    // --- host threefry: sampling column indices ---
    ColsAll cols;
    tfry::Key root{0u, 42u};
    tfry::Key kset[2] = {tfry::fold(root, 0), tfry::fold(root, 1)};
    for (int set = 0; set < 2; set++) {
        tfry::Key key = kset[set];
        {
            tfry::Key nk = tfry::fold(key, 0);
            tfry::Key p1 = tfry::fold(key, 1);
            tfry::Key p2 = tfry::fold(key, 2);
            tfry::perm64_prefix(p1, NN1, cols.out0[set]);
            tfry::perm64_prefix(p2, NN1, cols.in0[set]);
            key = nk;
        }
        {
            tfry::Key p1 = tfry::fold(key, 1);
            tfry::Key p2 = tfry::fold(key, 2);
            tfry::perm64_prefix(p1, NN0, cols.out1[set]);
            tfry::perm64_prefix(p2, NN0, cols.in1[set]);
        }
    }

    // --- pipeline: 3 launches ---
    comb_b1_prep<<<PREP_BLOCKS + B1_BLOCKS, 256>>>(nodes1, nodes2, nbr_out,
                                                   nbr_in, W_in, cols);        // #1
    fused_l0s1<<<L0_BLOCKS + S1_BLOCKS, 256, SMEM_FUSED>>>(feat, nodes1,
                                                           nodes2, nbr_out,
                                                           nbr_in, W_in, cols); // #2
    fused_s2<<<dim3(64, 1), 256>>>(W_mean, W_std, W_pi,
                                   Wd_mean, Wd_std, Wd_pi, out);               // #3
}

// round 15
// speedup vs baseline: 1.1891x; 1.1891x over previous
#include <cuda_runtime.h>
#include <cstdint>
#include <algorithm>

// ---------------------------------------------------------------------------
// Problem constants
// ---------------------------------------------------------------------------
#define BATCH   256
#define FDIM    128
#define EDIM    128
#define DDIM    64
#define MAXDEG  64
#define NN1     25
#define NN0     10
#define ROWS1   (BATCH * 2 * NN1)     // 12800 per set
#define ROWS2   (ROWS1 * 2 * NN0)     // 256000 per set
#define ROWS_BIG (2 * ROWS1)          // 25600
#define KDIM    384

#define RPB     64                    // rows per block in fused_l0
#define ASTRIDE 388                   // 384 + 4 pad -> conflict-free A-frag LDS
#define SM_A    (RPB * ASTRIDE)       // 24832 floats
#define BSZ     (8 * 128)             // one hi 8-k panel (1024 floats)
#define SM_B    (2 * BSZ)             // double-buffered hi panels
#define SMEM_FUSED ((SM_A + SM_B) * 4)   // 107520 B (2 blocks/SM)

#define L0_BLOCKS (ROWS_BIG / RPB)    // 400
#define S1_BLOCKS 64
#define PREP_BLOCKS (KDIM * EDIM / 256)   // 192
#define B1_BLOCKS ((2 * ROWS1 + 255) / 256) // 100

// ---------------------------------------------------------------------------
// Static device scratch
// ---------------------------------------------------------------------------
__device__ int   g_lvl1[2][ROWS1];
__device__ int   g_lvl2[2][ROWS2];
__device__ float g_h11[(size_t)ROWS_BIG * EDIM];      // 13.1 MB
__device__ float g_h10[2 * BATCH * EDIM];
__device__ float g_Whi[KDIM * EDIM];

struct ColsAll {
    int out0[2][NN1];
    int in0[2][NN1];
    int out1[2][NN0];
    int in1[2][NN0];
};

// ---------------------------------------------------------------------------
// Helpers
// ---------------------------------------------------------------------------
__device__ __forceinline__ float sigmoidf_stable(float x) {
    if (x >= 0.f) {
        return 1.f / (1.f + expf(-x));
    } else {
        float e = expf(x);
        return e / (1.f + e);
    }
}

__device__ __forceinline__ unsigned tf32_rna(float x) {
    unsigned r;
    asm("cvt.rna.tf32.f32 %0, %1;" : "=r"(r) : "f"(x));
    return r;
}

__device__ __forceinline__ void mma_tf32(float* c,
                                         unsigned a0, unsigned a1,
                                         unsigned a2, unsigned a3,
                                         unsigned b0, unsigned b1) {
    asm volatile(
        "mma.sync.aligned.m16n8k8.row.col.f32.tf32.tf32.f32 "
        "{%0,%1,%2,%3}, {%4,%5,%6,%7}, {%8,%9}, {%0,%1,%2,%3};"
        : "+f"(c[0]), "+f"(c[1]), "+f"(c[2]), "+f"(c[3])
        : "r"(a0), "r"(a1), "r"(a2), "r"(a3), "r"(b0), "r"(b1));
}

// ---------------------------------------------------------------------------
// #1: build_lvl1 + prep_w combined
// ---------------------------------------------------------------------------
__global__ void comb_b1_prep(const int* __restrict__ nodes1,
                             const int* __restrict__ nodes2,
                             const int* __restrict__ nbr_out,
                             const int* __restrict__ nbr_in,
                             const float* __restrict__ W,
                             ColsAll cols) {
    if (blockIdx.x < PREP_BLOCKS) {
        int idx = blockIdx.x * 256 + threadIdx.x;
        g_Whi[idx] = __uint_as_float(tf32_rna(W[idx]));
        return;
    }
    int tid = (blockIdx.x - PREP_BLOCKS) * 256 + threadIdx.x;
    const int total = 2 * ROWS1;
    if (tid >= total) return;
    int set = tid / ROWS1;
    int rem = tid - set * ROWS1;
    int i = rem / (2 * NN1);
    int j = rem - i * (2 * NN1);
    int node = (set ? nodes2 : nodes1)[i];
    int col;
    const int* nbr;
    if (j < NN1) { col = cols.out0[set][j];        nbr = nbr_out; }
    else         { col = cols.in0[set][j - NN1];   nbr = nbr_in;  }
    g_lvl1[set][rem] = nbr[(size_t)node * MAXDEG + col];
}

// ---------------------------------------------------------------------------
// #2: level-2 sampling indices (separate, fully-parallel launch — reverted)
// ---------------------------------------------------------------------------
__global__ void build_lvl2(const int* __restrict__ nbr_out,
                           const int* __restrict__ nbr_in,
                           ColsAll cols) {
    int tid = blockIdx.x * blockDim.x + threadIdx.x;
    const int total = 2 * ROWS2;
    if (tid >= total) return;
    int set = tid / ROWS2;
    int rem = tid - set * ROWS2;
    int r = rem / (2 * NN0);
    int j = rem - r * (2 * NN0);
    int parent = g_lvl1[set][r];
    int col;
    const int* nbr;
    if (j < NN0) { col = cols.out1[set][j];        nbr = nbr_out; }
    else         { col = cols.in1[set][j - NN0];   nbr = nbr_in;  }
    g_lvl2[set][rem] = nbr[(size_t)parent * MAXDEG + col];
}

// ---------------------------------------------------------------------------
// #3: fused_l0 (blocks 0..399) + fused_s1 (400..463) in one launch
// ---------------------------------------------------------------------------
__global__ void __launch_bounds__(256, 2)
fused_l0s1(const float* __restrict__ feat,
           const int* __restrict__ nodes1,
           const int* __restrict__ nodes2,
           const float* __restrict__ W) {
    extern __shared__ float sm[];
    const int t    = threadIdx.x;
    const int lane = t & 31;
    const int w    = t >> 5;

    const float4* feat4 = reinterpret_cast<const float4*>(feat);

    if (blockIdx.x >= L0_BLOCKS) {
        // ================== fused_s1 path ==================
        float* As = sm;                       // [8][ASTRIDE]
        float* Bs = sm + 8 * ASTRIDE;         // [16][128]
        const int b = blockIdx.x - L0_BLOCKS; // 0..63

        {   // gather: warp w -> row w
            int R = b * 8 + w;                // 0..511
            int set = R >> 8, i = R & 255;
            int self = (set ? nodes2 : nodes1)[i];
            const int* l1 = &g_lvl1[set][i * 2 * NN1];
            const float inv = 1.0f / (float)NN1;

            float4 vs = feat4[(size_t)self * 32 + lane];
            float4 ao = make_float4(0.f, 0.f, 0.f, 0.f);
            float4 ai = make_float4(0.f, 0.f, 0.f, 0.f);
#pragma unroll
            for (int j = 0; j < NN1; j++) {
                float4 v = feat4[(size_t)l1[j] * 32 + lane];
                ao.x += v.x; ao.y += v.y; ao.z += v.z; ao.w += v.w;
            }
#pragma unroll
            for (int j = NN1; j < 2 * NN1; j++) {
                float4 v = feat4[(size_t)l1[j] * 32 + lane];
                ai.x += v.x; ai.y += v.y; ai.z += v.z; ai.w += v.w;
            }
            float* arow = &As[w * ASTRIDE];
            *reinterpret_cast<float4*>(&arow[lane * 4]) = vs;
            *reinterpret_cast<float4*>(&arow[128 + lane * 4]) =
                make_float4(ao.x * inv, ao.y * inv, ao.z * inv, ao.w * inv);
            *reinterpret_cast<float4*>(&arow[256 + lane * 4]) =
                make_float4(ai.x * inv, ai.y * inv, ai.z * inv, ai.w * inv);
        }
        __syncthreads();

        const int tx = t & 31;
        float acc[4] = {0.f, 0.f, 0.f, 0.f};
        for (int k0 = 0; k0 < KDIM; k0 += 16) {
#pragma unroll
            for (int l = 0; l < 2; l++) {
                int f4 = t * 2 + l;
                int k  = f4 >> 5;
                int c  = (f4 & 31) * 4;
                *reinterpret_cast<float4*>(&Bs[k * 128 + c]) =
                    *reinterpret_cast<const float4*>(&W[(size_t)(k0 + k) * EDIM + c]);
            }
            __syncthreads();
#pragma unroll
            for (int k = 0; k < 16; k++) {
                float4 bv = *reinterpret_cast<const float4*>(&Bs[k * 128 + tx * 4]);
                float a = As[w * ASTRIDE + k0 + k];
                acc[0] += a * bv.x; acc[1] += a * bv.y;
                acc[2] += a * bv.z; acc[3] += a * bv.w;
            }
            __syncthreads();
        }
        int R = b * 8 + w;
        float4 o;
        o.x = sigmoidf_stable(acc[0]);
        o.y = sigmoidf_stable(acc[1]);
        o.z = sigmoidf_stable(acc[2]);
        o.w = sigmoidf_stable(acc[3]);
        *reinterpret_cast<float4*>(&g_h10[(size_t)R * EDIM + tx * 4]) = o;
        return;
    }

    // ================== fused_l0 path ==================
    float* As = sm;                 // [RPB][ASTRIDE]
    float* Bs = sm + SM_A;          // [2 buf][8][128] swizzled (hi only)
    const int r0 = blockIdx.x * RPB;

    // ---- Phase 1: gather + mean into smem (indices from g_lvl2) ----
    const float inv = 1.0f / (float)NN0;
#pragma unroll
    for (int rr = 0; rr < RPB / 8; rr++) {
        int r = w * (RPB / 8) + rr;
        int R = r0 + r;
        int set = (R >= ROWS1) ? 1 : 0;
        int i = R - set * ROWS1;
        int self = g_lvl1[set][i];
        const int* l2 = &g_lvl2[set][i * 2 * NN0];

        float4 vs = feat4[(size_t)self * 32 + lane];
        float4 ao = make_float4(0.f, 0.f, 0.f, 0.f);
        float4 ai = make_float4(0.f, 0.f, 0.f, 0.f);
#pragma unroll
        for (int j = 0; j < NN0; j++) {
            float4 v = feat4[(size_t)l2[j] * 32 + lane];
            ao.x += v.x; ao.y += v.y; ao.z += v.z; ao.w += v.w;
        }
#pragma unroll
        for (int j = NN0; j < 2 * NN0; j++) {
            float4 v = feat4[(size_t)l2[j] * 32 + lane];
            ai.x += v.x; ai.y += v.y; ai.z += v.z; ai.w += v.w;
        }
        float* arow = &As[r * ASTRIDE];
        *reinterpret_cast<float4*>(&arow[lane * 4]) = vs;
        float4 mo = make_float4(ao.x * inv, ao.y * inv, ao.z * inv, ao.w * inv);
        float4 mi = make_float4(ai.x * inv, ai.y * inv, ai.z * inv, ai.w * inv);
        *reinterpret_cast<float4*>(&arow[128 + lane * 4]) = mo;
        *reinterpret_cast<float4*>(&arow[256 + lane * 4]) = mi;
    }

    // ---- Phase 2: 2-term TF32 MMA, double-buffered B, pipelined A frags ----
    const int group = lane >> 2;
    const int tid4  = lane & 3;
    const int R0w   = (w & 3) * 16;
    const int C0    = (w >> 2) * 64;

    float acc[8][4];
#pragma unroll
    for (int j = 0; j < 8; j++)
#pragma unroll
        for (int q = 0; q < 4; q++) acc[j][q] = 0.f;

    const int pk = t >> 5;
    const int pn = (t & 31) * 4;
    const int sb = pk * 128 + (pn ^ (pk * 8));

    const int ob0 = tid4 * 128;
    const int ob1 = (tid4 + 4) * 128;
    const int xr0 = tid4 * 8;
    const int xr1 = (tid4 + 4) * 8;

    const float* arb  = &As[(R0w + group) * ASTRIDE];
    const float* arb8 = arb + 8 * ASTRIDE;

    float4 whi = *reinterpret_cast<const float4*>(&g_Whi[pk * EDIM + pn]);
    __syncthreads();   // As complete

    float x00 = arb[tid4];
    float x10 = arb8[tid4];
    float x01 = arb[tid4 + 4];
    float x11 = arb8[tid4 + 4];

    *reinterpret_cast<float4*>(&Bs[sb]) = whi;                   // panel 0 -> buf 0
    whi = *reinterpret_cast<const float4*>(&g_Whi[(8 + pk) * EDIM + pn]);
    __syncthreads();   // buf 0 visible

    const int NP = KDIM / 8;   // 48
    for (int p = 0; p < NP; p++) {
        const float* buf = &Bs[(p & 1) * BSZ];

        if (p + 1 < NP) {
            *reinterpret_cast<float4*>(&Bs[((p + 1) & 1) * BSZ + sb]) = whi;
            if (p + 2 < NP) {
                whi = *reinterpret_cast<const float4*>(
                    &g_Whi[((p + 2) * 8 + pk) * EDIM + pn]);
            }
        }

        unsigned ah0 = tf32_rna(x00), ah1 = tf32_rna(x10),
                 ah2 = tf32_rna(x01), ah3 = tf32_rna(x11);
        unsigned al0 = tf32_rna(x00 - __uint_as_float(ah0));
        unsigned al1 = tf32_rna(x10 - __uint_as_float(ah1));
        unsigned al2 = tf32_rna(x01 - __uint_as_float(ah2));
        unsigned al3 = tf32_rna(x11 - __uint_as_float(ah3));

        if (p + 1 < NP) {
            int ko = (p + 1) * 8;
            x00 = arb[ko + tid4];
            x10 = arb8[ko + tid4];
            x01 = arb[ko + tid4 + 4];
            x11 = arb8[ko + tid4 + 4];
        }

#pragma unroll
        for (int j = 0; j < 8; j++) {
            int nl = C0 + j * 8 + group;
            unsigned bh0 = __float_as_uint(buf[ob0 + (nl ^ xr0)]);
            unsigned bh1 = __float_as_uint(buf[ob1 + (nl ^ xr1)]);
            mma_tf32(acc[j], ah0, ah1, ah2, ah3, bh0, bh1);
            mma_tf32(acc[j], al0, al1, al2, al3, bh0, bh1);
        }
        __syncthreads();
    }

    // ---- Epilogue: sigmoid + store ----
    const int Ra = r0 + R0w + group;
    const int Rb = Ra + 8;
#pragma unroll
    for (int j = 0; j < 8; j++) {
        int col = C0 + j * 8 + 2 * tid4;
        float2 oa, ob;
        oa.x = sigmoidf_stable(acc[j][0]);
        oa.y = sigmoidf_stable(acc[j][1]);
        ob.x = sigmoidf_stable(acc[j][2]);
        ob.y = sigmoidf_stable(acc[j][3]);
        *reinterpret_cast<float2*>(&g_h11[(size_t)Ra * EDIM + col]) = oa;
        *reinterpret_cast<float2*>(&g_h11[(size_t)Rb * EDIM + col]) = ob;
    }
}

// ---------------------------------------------------------------------------
// #4: fused_s2: layer-1 agg ONCE + 3 heads (GEMM+sigmoid+proj) -> out
// Grid 64, block 256; 8 rows per block. W panels prefetched into registers.
// ---------------------------------------------------------------------------
__global__ void __launch_bounds__(256)
fused_s2(const float* __restrict__ Wm, const float* __restrict__ Ws,
         const float* __restrict__ Wp,
         const float* __restrict__ Wdm, const float* __restrict__ Wds,
         const float* __restrict__ Wdp,
         float* __restrict__ out) {
    __shared__ float As[8 * ASTRIDE];
    __shared__ float Bs[16 * 128];
    __shared__ float Hs[8 * 132];

    const int t = threadIdx.x, lane = t & 31, w = t >> 5;

    // Panel-load index for this thread (32 float4 per 16x128 panel slice / 2)
    const int pk0 = (t * 2) >> 5;
    const int pc0 = ((t * 2) & 31) * 4;
    const int pk1 = (t * 2 + 1) >> 5;
    const int pc1 = ((t * 2 + 1) & 31) * 4;

    const float* Wh[3]  = {Wm, Ws, Wp};
    const float* Wdh[3] = {Wdm, Wds, Wdp};

    // ---- layer-1 aggregation ONCE (warp w -> row w) ----
    {
        int R = blockIdx.x * 8 + w;
        int set = R >> 8, i = R & 255;
        const float4* h4 = reinterpret_cast<const float4*>(
            &g_h11[(size_t)(set * ROWS1 + i * 2 * NN1) * EDIM]);
        const float inv = 1.0f / (float)NN1;

        float4 vs = reinterpret_cast<const float4*>(&g_h10[(size_t)R * EDIM])[lane];
        float4 ao = make_float4(0.f, 0.f, 0.f, 0.f);
        float4 ai = make_float4(0.f, 0.f, 0.f, 0.f);
#pragma unroll
        for (int j = 0; j < NN1; j++) {
            float4 v = h4[(size_t)j * 32 + lane];
            ao.x += v.x; ao.y += v.y; ao.z += v.z; ao.w += v.w;
        }
#pragma unroll
        for (int j = NN1; j < 2 * NN1; j++) {
            float4 v = h4[(size_t)j * 32 + lane];
            ai.x += v.x; ai.y += v.y; ai.z += v.z; ai.w += v.w;
        }
        float* arow = &As[w * ASTRIDE];
        *reinterpret_cast<float4*>(&arow[lane * 4]) = vs;
        *reinterpret_cast<float4*>(&arow[128 + lane * 4]) =
            make_float4(ao.x * inv, ao.y * inv, ao.z * inv, ao.w * inv);
        *reinterpret_cast<float4*>(&arow[256 + lane * 4]) =
            make_float4(ai.x * inv, ai.y * inv, ai.z * inv, ai.w * inv);
    }

    const int tx = t & 31;

    // Prefetch first panel of head 0 (overlaps with aggregation tail)
    float4 wv0 = *reinterpret_cast<const float4*>(&Wh[0][(size_t)pk0 * EDIM + pc0]);
    float4 wv1 = *reinterpret_cast<const float4*>(&Wh[0][(size_t)pk1 * EDIM + pc1]);
    __syncthreads();

    for (int head = 0; head < 3; head++) {
        const float* W  = Wh[head];
        const float* Wd = Wdh[head];

        // ---- head GEMM + sigmoid -> Hs (reg-prefetched W panels) ----
        float acc[4] = {0.f, 0.f, 0.f, 0.f};
        for (int k0 = 0; k0 < KDIM; k0 += 16) {
            *reinterpret_cast<float4*>(&Bs[pk0 * 128 + pc0]) = wv0;
            *reinterpret_cast<float4*>(&Bs[pk1 * 128 + pc1]) = wv1;
            __syncthreads();

            // prefetch next panel (same head, or head+1's first panel)
            if (k0 + 16 < KDIM) {
                wv0 = *reinterpret_cast<const float4*>(
                    &W[(size_t)(k0 + 16 + pk0) * EDIM + pc0]);
                wv1 = *reinterpret_cast<const float4*>(
                    &W[(size_t)(k0 + 16 + pk1) * EDIM + pc1]);
            } else if (head + 1 < 3) {
                wv0 = *reinterpret_cast<const float4*>(
                    &Wh[head + 1][(size_t)pk0 * EDIM + pc0]);
                wv1 = *reinterpret_cast<const float4*>(
                    &Wh[head + 1][(size_t)pk1 * EDIM + pc1]);
            }

#pragma unroll
            for (int k = 0; k < 16; k++) {
                float4 b = *reinterpret_cast<const float4*>(&Bs[k * 128 + tx * 4]);
                float a = As[w * ASTRIDE + k0 + k];
                acc[0] += a * b.x; acc[1] += a * b.y;
                acc[2] += a * b.z; acc[3] += a * b.w;
            }
            __syncthreads();
        }

        {
            float4 o;
            o.x = sigmoidf_stable(acc[0]);
            o.y = sigmoidf_stable(acc[1]);
            o.z = sigmoidf_stable(acc[2]);
            o.w = sigmoidf_stable(acc[3]);
            *reinterpret_cast<float4*>(&Hs[w * 132 + tx * 4]) = o;
        }
        __syncthreads();

        // ---- projection: z[8][64] = Hs[8][128] @ Wd[128][64] ----
        {
            int r  = t >> 5;
            int cg = t & 31;
            float s0 = 0.f, s1 = 0.f;
#pragma unroll
            for (int k = 0; k < 128; k++) {
                float hv = Hs[r * 132 + k];
                float2 wd = *reinterpret_cast<const float2*>(&Wd[k * DDIM + cg * 2]);
                s0 += hv * wd.x;
                s1 += hv * wd.y;
            }
            int R = blockIdx.x * 8 + r;
            int set = R >> 8, i = R & 255;
            float2 z = make_float2(s0, s1);
            *reinterpret_cast<float2*>(
                &out[((size_t)(set * 3 + head) * BATCH + i) * DDIM + cg * 2]) = z;
        }
        __syncthreads();   // Hs/Bs reuse by next head
    }
}

// ---------------------------------------------------------------------------
// Host-side JAX threefry reproduction (partitionable mode)
// ---------------------------------------------------------------------------
namespace tfry {

static inline uint32_t rotl32(uint32_t x, int d) { return (x << d) | (x >> (32 - d)); }

struct Key { uint32_t a, b; };

static Key threefry2x32(Key k, uint32_t x0, uint32_t x1) {
    uint32_t ks0 = k.a, ks1 = k.b, ks2 = k.a ^ k.b ^ 0x1BD11BDAu;
    x0 += ks0; x1 += ks1;
    static const int R0[4] = {13, 15, 26, 6};
    static const int R1[4] = {17, 29, 16, 24};
    auto rounds4 = [&](const int* R) {
        for (int i = 0; i < 4; i++) { x0 += x1; x1 = rotl32(x1, R[i]); x1 ^= x0; }
    };
    rounds4(R0); x0 += ks1; x1 += ks2 + 1u;
    rounds4(R1); x0 += ks2; x1 += ks0 + 2u;
    rounds4(R0); x0 += ks0; x1 += ks1 + 3u;
    rounds4(R1); x0 += ks1; x1 += ks2 + 4u;
    rounds4(R0); x0 += ks2; x1 += ks0 + 5u;
    return Key{x0, x1};
}

static Key fold(Key k, uint32_t i) { return threefry2x32(k, 0u, i); }

static void perm64_prefix(Key key, int n, int* out) {
    Key subkey = fold(key, 1);
    uint32_t bits[64];
    int idx[64];
    for (int i = 0; i < 64; i++) {
        Key r = threefry2x32(subkey, 0u, (uint32_t)i);
        bits[i] = r.a ^ r.b;
        idx[i] = i;
    }
    std::stable_sort(idx, idx + 64,
                     [&](int x, int y) { return bits[x] < bits[y]; });
    for (int j = 0; j < n; j++) out[j] = idx[j];
}

}  // namespace tfry

// ---------------------------------------------------------------------------
// kernel_launch
// ---------------------------------------------------------------------------
extern "C" void kernel_launch(void* const* d_in, const int* in_sizes, int n_in,
                              void* d_out, int out_size) {
    const int*   nodes1  = (const int*)d_in[0];
    const int*   nodes2  = (const int*)d_in[1];
    const int*   nbr_out = (const int*)d_in[2];
    const int*   nbr_in  = (const int*)d_in[3];
    const float* feat    = (const float*)d_in[4];
    const float* W_in    = (const float*)d_in[5];
    const float* W_mean  = (const float*)d_in[6];
    const float* W_std   = (const float*)d_in[7];
    const float* W_pi    = (const float*)d_in[8];
    const float* Wd_mean = (const float*)d_in[11];
    const float* Wd_std  = (const float*)d_in[12];
    const float* Wd_pi   = (const float*)d_in[13];
    float* out = (float*)d_out;

    cudaFuncSetAttribute(fused_l0s1, cudaFuncAttributeMaxDynamicSharedMemorySize,
                         SMEM_FUSED);

    // --- host threefry: sampling column indices ---
    ColsAll cols;
    tfry::Key root{0u, 42u};
    tfry::Key kset[2] = {tfry::fold(root, 0), tfry::fold(root, 1)};
    for (int set = 0; set < 2; set++) {
        tfry::Key key = kset[set];
        {
            tfry::Key nk = tfry::fold(key, 0);
            tfry::Key p1 = tfry::fold(key, 1);
            tfry::Key p2 = tfry::fold(key, 2);
            tfry::perm64_prefix(p1, NN1, cols.out0[set]);
            tfry::perm64_prefix(p2, NN1, cols.in0[set]);
            key = nk;
        }
        {
            tfry::Key p1 = tfry::fold(key, 1);
            tfry::Key p2 = tfry::fold(key, 2);
            tfry::perm64_prefix(p1, NN0, cols.out1[set]);
            tfry::perm64_prefix(p2, NN0, cols.in1[set]);
        }
    }

    // --- pipeline: 4 launches ---
    comb_b1_prep<<<PREP_BLOCKS + B1_BLOCKS, 256>>>(nodes1, nodes2, nbr_out,
                                                   nbr_in, W_in, cols);        // #1
    build_lvl2<<<(2 * ROWS2 + 255) / 256, 256>>>(nbr_out, nbr_in, cols);       // #2
    fused_l0s1<<<L0_BLOCKS + S1_BLOCKS, 256, SMEM_FUSED>>>(feat, nodes1,
                                                           nodes2, W_in);      // #3
    fused_s2<<<dim3(64, 1), 256>>>(W_mean, W_std, W_pi,
                                   Wd_mean, Wd_std, Wd_pi, out);               // #4
}

// round 17
// speedup vs baseline: 1.5953x; 1.3415x over previous
#include <cuda_runtime.h>
#include <cstdint>
#include <algorithm>

// ---------------------------------------------------------------------------
// Problem constants
// ---------------------------------------------------------------------------
#define BATCH   256
#define FDIM    128
#define EDIM    128
#define DDIM    64
#define MAXDEG  64
#define NN1     25
#define NN0     10
#define ROWS1   (BATCH * 2 * NN1)     // 12800 per set
#define ROWS2   (ROWS1 * 2 * NN0)     // 256000 per set
#define ROWS_BIG (2 * ROWS1)          // 25600
#define KDIM    384

#define RPB     64                    // rows per block in fused_l0
#define ASTRIDE 388                   // 384 + 4 pad -> conflict-free A-frag LDS
#define SM_A    (RPB * ASTRIDE)       // 24832 floats
#define BSZ     (8 * 128)             // one hi 8-k panel (1024 floats)
#define SM_B    (2 * BSZ)             // double-buffered hi panels
#define SMEM_FUSED ((SM_A + SM_B) * 4)   // 107520 B (2 blocks/SM)

#define L0_BLOCKS (ROWS_BIG / RPB)    // 400
#define S1_BLOCKS 64
#define PREP_BLOCKS (KDIM * EDIM / 256)   // 192
#define B1_BLOCKS ((2 * ROWS1 + 255) / 256) // 100

// ---------------------------------------------------------------------------
// Static device scratch
// ---------------------------------------------------------------------------
__device__ int   g_lvl1[2][ROWS1];
__device__ int   g_lvl2[2][ROWS2];
__device__ float g_h11[(size_t)ROWS_BIG * EDIM];      // 13.1 MB
__device__ float g_h10[2 * BATCH * EDIM];
__device__ float g_aggL1[2 * BATCH * KDIM];           // 786 KB (L2-resident)
__device__ float g_Whi[KDIM * EDIM];

struct ColsAll {
    int out0[2][NN1];
    int in0[2][NN1];
    int out1[2][NN0];
    int in1[2][NN0];
};

// ---------------------------------------------------------------------------
// Helpers
// ---------------------------------------------------------------------------
__device__ __forceinline__ float sigmoidf_stable(float x) {
    if (x >= 0.f) {
        return 1.f / (1.f + expf(-x));
    } else {
        float e = expf(x);
        return e / (1.f + e);
    }
}

__device__ __forceinline__ unsigned tf32_rna(float x) {
    unsigned r;
    asm("cvt.rna.tf32.f32 %0, %1;" : "=r"(r) : "f"(x));
    return r;
}

__device__ __forceinline__ void mma_tf32(float* c,
                                         unsigned a0, unsigned a1,
                                         unsigned a2, unsigned a3,
                                         unsigned b0, unsigned b1) {
    asm volatile(
        "mma.sync.aligned.m16n8k8.row.col.f32.tf32.tf32.f32 "
        "{%0,%1,%2,%3}, {%4,%5,%6,%7}, {%8,%9}, {%0,%1,%2,%3};"
        : "+f"(c[0]), "+f"(c[1]), "+f"(c[2]), "+f"(c[3])
        : "r"(a0), "r"(a1), "r"(a2), "r"(a3), "r"(b0), "r"(b1));
}

// ---------------------------------------------------------------------------
// #1: build_lvl1 + prep_w combined
// ---------------------------------------------------------------------------
__global__ void comb_b1_prep(const int* __restrict__ nodes1,
                             const int* __restrict__ nodes2,
                             const int* __restrict__ nbr_out,
                             const int* __restrict__ nbr_in,
                             const float* __restrict__ W,
                             ColsAll cols) {
    if (blockIdx.x < PREP_BLOCKS) {
        int idx = blockIdx.x * 256 + threadIdx.x;
        g_Whi[idx] = __uint_as_float(tf32_rna(W[idx]));
        return;
    }
    int tid = (blockIdx.x - PREP_BLOCKS) * 256 + threadIdx.x;
    const int total = 2 * ROWS1;
    if (tid >= total) return;
    int set = tid / ROWS1;
    int rem = tid - set * ROWS1;
    int i = rem / (2 * NN1);
    int j = rem - i * (2 * NN1);
    int node = (set ? nodes2 : nodes1)[i];
    int col;
    const int* nbr;
    if (j < NN1) { col = cols.out0[set][j];        nbr = nbr_out; }
    else         { col = cols.in0[set][j - NN1];   nbr = nbr_in;  }
    g_lvl1[set][rem] = nbr[(size_t)node * MAXDEG + col];
}

// ---------------------------------------------------------------------------
// #2: level-2 sampling indices (fully-parallel)
// ---------------------------------------------------------------------------
__global__ void build_lvl2(const int* __restrict__ nbr_out,
                           const int* __restrict__ nbr_in,
                           ColsAll cols) {
    int tid = blockIdx.x * blockDim.x + threadIdx.x;
    const int total = 2 * ROWS2;
    if (tid >= total) return;
    int set = tid / ROWS2;
    int rem = tid - set * ROWS2;
    int r = rem / (2 * NN0);
    int j = rem - r * (2 * NN0);
    int parent = g_lvl1[set][r];
    int col;
    const int* nbr;
    if (j < NN0) { col = cols.out1[set][j];        nbr = nbr_out; }
    else         { col = cols.in1[set][j - NN0];   nbr = nbr_in;  }
    g_lvl2[set][rem] = nbr[(size_t)parent * MAXDEG + col];
}

// ---------------------------------------------------------------------------
// #3: fused_l0 (blocks 0..399) + fused_s1 (400..463) in one launch
// ---------------------------------------------------------------------------
__global__ void __launch_bounds__(256, 2)
fused_l0s1(const float* __restrict__ feat,
           const int* __restrict__ nodes1,
           const int* __restrict__ nodes2,
           const float* __restrict__ W) {
    extern __shared__ float sm[];
    const int t    = threadIdx.x;
    const int lane = t & 31;
    const int w    = t >> 5;

    const float4* feat4 = reinterpret_cast<const float4*>(feat);

    if (blockIdx.x >= L0_BLOCKS) {
        // ================== fused_s1 path ==================
        float* As = sm;                       // [8][ASTRIDE]
        float* Bs = sm + 8 * ASTRIDE;         // [16][128]
        const int b = blockIdx.x - L0_BLOCKS; // 0..63

        {   // gather: warp w -> row w
            int R = b * 8 + w;                // 0..511
            int set = R >> 8, i = R & 255;
            int self = (set ? nodes2 : nodes1)[i];
            const int* l1 = &g_lvl1[set][i * 2 * NN1];
            const float inv = 1.0f / (float)NN1;

            float4 vs = feat4[(size_t)self * 32 + lane];
            float4 ao = make_float4(0.f, 0.f, 0.f, 0.f);
            float4 ai = make_float4(0.f, 0.f, 0.f, 0.f);
#pragma unroll
            for (int j = 0; j < NN1; j++) {
                float4 v = feat4[(size_t)l1[j] * 32 + lane];
                ao.x += v.x; ao.y += v.y; ao.z += v.z; ao.w += v.w;
            }
#pragma unroll
            for (int j = NN1; j < 2 * NN1; j++) {
                float4 v = feat4[(size_t)l1[j] * 32 + lane];
                ai.x += v.x; ai.y += v.y; ai.z += v.z; ai.w += v.w;
            }
            float* arow = &As[w * ASTRIDE];
            *reinterpret_cast<float4*>(&arow[lane * 4]) = vs;
            *reinterpret_cast<float4*>(&arow[128 + lane * 4]) =
                make_float4(ao.x * inv, ao.y * inv, ao.z * inv, ao.w * inv);
            *reinterpret_cast<float4*>(&arow[256 + lane * 4]) =
                make_float4(ai.x * inv, ai.y * inv, ai.z * inv, ai.w * inv);
        }
        __syncthreads();

        const int tx = t & 31;
        float acc[4] = {0.f, 0.f, 0.f, 0.f};
        for (int k0 = 0; k0 < KDIM; k0 += 16) {
#pragma unroll
            for (int l = 0; l < 2; l++) {
                int f4 = t * 2 + l;
                int k  = f4 >> 5;
                int c  = (f4 & 31) * 4;
                *reinterpret_cast<float4*>(&Bs[k * 128 + c]) =
                    *reinterpret_cast<const float4*>(&W[(size_t)(k0 + k) * EDIM + c]);
            }
            __syncthreads();
#pragma unroll
            for (int k = 0; k < 16; k++) {
                float4 bv = *reinterpret_cast<const float4*>(&Bs[k * 128 + tx * 4]);
                float a = As[w * ASTRIDE + k0 + k];
                acc[0] += a * bv.x; acc[1] += a * bv.y;
                acc[2] += a * bv.z; acc[3] += a * bv.w;
            }
            __syncthreads();
        }
        int R = b * 8 + w;
        float4 o;
        o.x = sigmoidf_stable(acc[0]);
        o.y = sigmoidf_stable(acc[1]);
        o.z = sigmoidf_stable(acc[2]);
        o.w = sigmoidf_stable(acc[3]);
        *reinterpret_cast<float4*>(&g_h10[(size_t)R * EDIM + tx * 4]) = o;
        return;
    }

    // ================== fused_l0 path ==================
    float* As = sm;                 // [RPB][ASTRIDE]
    float* Bs = sm + SM_A;          // [2 buf][8][128] swizzled (hi only)
    const int r0 = blockIdx.x * RPB;

    // ---- Phase 1: gather + mean into smem (indices from g_lvl2) ----
    const float inv = 1.0f / (float)NN0;
#pragma unroll
    for (int rr = 0; rr < RPB / 8; rr++) {
        int r = w * (RPB / 8) + rr;
        int R = r0 + r;
        int set = (R >= ROWS1) ? 1 : 0;
        int i = R - set * ROWS1;
        int self = g_lvl1[set][i];
        const int* l2 = &g_lvl2[set][i * 2 * NN0];

        float4 vs = feat4[(size_t)self * 32 + lane];
        float4 ao = make_float4(0.f, 0.f, 0.f, 0.f);
        float4 ai = make_float4(0.f, 0.f, 0.f, 0.f);
#pragma unroll
        for (int j = 0; j < NN0; j++) {
            float4 v = feat4[(size_t)l2[j] * 32 + lane];
            ao.x += v.x; ao.y += v.y; ao.z += v.z; ao.w += v.w;
        }
#pragma unroll
        for (int j = NN0; j < 2 * NN0; j++) {
            float4 v = feat4[(size_t)l2[j] * 32 + lane];
            ai.x += v.x; ai.y += v.y; ai.z += v.z; ai.w += v.w;
        }
        float* arow = &As[r * ASTRIDE];
        *reinterpret_cast<float4*>(&arow[lane * 4]) = vs;
        float4 mo = make_float4(ao.x * inv, ao.y * inv, ao.z * inv, ao.w * inv);
        float4 mi = make_float4(ai.x * inv, ai.y * inv, ai.z * inv, ai.w * inv);
        *reinterpret_cast<float4*>(&arow[128 + lane * 4]) = mo;
        *reinterpret_cast<float4*>(&arow[256 + lane * 4]) = mi;
    }

    // ---- Phase 2: 2-term TF32 MMA, double-buffered B, pipelined A frags ----
    const int group = lane >> 2;
    const int tid4  = lane & 3;
    const int R0w   = (w & 3) * 16;
    const int C0    = (w >> 2) * 64;

    float acc[8][4];
#pragma unroll
    for (int j = 0; j < 8; j++)
#pragma unroll
        for (int q = 0; q < 4; q++) acc[j][q] = 0.f;

    const int pk = t >> 5;
    const int pn = (t & 31) * 4;
    const int sb = pk * 128 + (pn ^ (pk * 8));

    const int ob0 = tid4 * 128;
    const int ob1 = (tid4 + 4) * 128;
    const int xr0 = tid4 * 8;
    const int xr1 = (tid4 + 4) * 8;

    const float* arb  = &As[(R0w + group) * ASTRIDE];
    const float* arb8 = arb + 8 * ASTRIDE;

    float4 whi = *reinterpret_cast<const float4*>(&g_Whi[pk * EDIM + pn]);
    __syncthreads();   // As complete

    float x00 = arb[tid4];
    float x10 = arb8[tid4];
    float x01 = arb[tid4 + 4];
    float x11 = arb8[tid4 + 4];

    *reinterpret_cast<float4*>(&Bs[sb]) = whi;                   // panel 0 -> buf 0
    whi = *reinterpret_cast<const float4*>(&g_Whi[(8 + pk) * EDIM + pn]);
    __syncthreads();   // buf 0 visible

    const int NP = KDIM / 8;   // 48
    for (int p = 0; p < NP; p++) {
        const float* buf = &Bs[(p & 1) * BSZ];

        if (p + 1 < NP) {
            *reinterpret_cast<float4*>(&Bs[((p + 1) & 1) * BSZ + sb]) = whi;
            if (p + 2 < NP) {
                whi = *reinterpret_cast<const float4*>(
                    &g_Whi[((p + 2) * 8 + pk) * EDIM + pn]);
            }
        }

        unsigned ah0 = tf32_rna(x00), ah1 = tf32_rna(x10),
                 ah2 = tf32_rna(x01), ah3 = tf32_rna(x11);
        unsigned al0 = tf32_rna(x00 - __uint_as_float(ah0));
        unsigned al1 = tf32_rna(x10 - __uint_as_float(ah1));
        unsigned al2 = tf32_rna(x01 - __uint_as_float(ah2));
        unsigned al3 = tf32_rna(x11 - __uint_as_float(ah3));

        if (p + 1 < NP) {
            int ko = (p + 1) * 8;
            x00 = arb[ko + tid4];
            x10 = arb8[ko + tid4];
            x01 = arb[ko + tid4 + 4];
            x11 = arb8[ko + tid4 + 4];
        }

#pragma unroll
        for (int j = 0; j < 8; j++) {
            int nl = C0 + j * 8 + group;
            unsigned bh0 = __float_as_uint(buf[ob0 + (nl ^ xr0)]);
            unsigned bh1 = __float_as_uint(buf[ob1 + (nl ^ xr1)]);
            mma_tf32(acc[j], ah0, ah1, ah2, ah3, bh0, bh1);
            mma_tf32(acc[j], al0, al1, al2, al3, bh0, bh1);
        }
        __syncthreads();
    }

    // ---- Epilogue: sigmoid + store ----
    const int Ra = r0 + R0w + group;
    const int Rb = Ra + 8;
#pragma unroll
    for (int j = 0; j < 8; j++) {
        int col = C0 + j * 8 + 2 * tid4;
        float2 oa, ob;
        oa.x = sigmoidf_stable(acc[j][0]);
        oa.y = sigmoidf_stable(acc[j][1]);
        ob.x = sigmoidf_stable(acc[j][2]);
        ob.y = sigmoidf_stable(acc[j][3]);
        *reinterpret_cast<float2*>(&g_h11[(size_t)Ra * EDIM + col]) = oa;
        *reinterpret_cast<float2*>(&g_h11[(size_t)Rb * EDIM + col]) = ob;
    }
}

// ---------------------------------------------------------------------------
// #4: agg_l1: layer-1 aggregation -> g_aggL1 (once, max parallelism)
// Grid 64, block 256; warp per row.
// ---------------------------------------------------------------------------
__global__ void agg_l1() {
    int t = threadIdx.x, lane = t & 31, w = t >> 5;
    int r = blockIdx.x * 8 + w;          // 0..511
    int set = r >> 8, i = r & 255;
    const float4* h4 = reinterpret_cast<const float4*>(
        &g_h11[(size_t)(set * ROWS1 + i * 2 * NN1) * EDIM]);
    const float inv = 1.0f / (float)NN1;

    float4 ao = make_float4(0.f, 0.f, 0.f, 0.f);
    float4 ai = make_float4(0.f, 0.f, 0.f, 0.f);
#pragma unroll
    for (int j = 0; j < NN1; j++) {
        float4 v = h4[(size_t)j * 32 + lane];
        ao.x += v.x; ao.y += v.y; ao.z += v.z; ao.w += v.w;
    }
#pragma unroll
    for (int j = NN1; j < 2 * NN1; j++) {
        float4 v = h4[(size_t)j * 32 + lane];
        ai.x += v.x; ai.y += v.y; ai.z += v.z; ai.w += v.w;
    }
    float4 vs = reinterpret_cast<const float4*>(&g_h10[(size_t)r * EDIM])[lane];
    float* a = &g_aggL1[(size_t)r * KDIM];
    *reinterpret_cast<float4*>(&a[lane * 4]) = vs;
    *reinterpret_cast<float4*>(&a[128 + lane * 4]) =
        make_float4(ao.x * inv, ao.y * inv, ao.z * inv, ao.w * inv);
    *reinterpret_cast<float4*>(&a[256 + lane * 4]) =
        make_float4(ai.x * inv, ai.y * inv, ai.z * inv, ai.w * inv);
}

// ---------------------------------------------------------------------------
// #5: head_proj: per-head GEMM+sigmoid+projection from g_aggL1 -> out
// Grid (32, 3): blockIdx.x = 16-row M-tile, blockIdx.y = head.
// ---------------------------------------------------------------------------
__global__ void __launch_bounds__(256)
head_proj(const float* __restrict__ Wm, const float* __restrict__ Ws,
          const float* __restrict__ Wp,
          const float* __restrict__ Wdm, const float* __restrict__ Wds,
          const float* __restrict__ Wdp,
          float* __restrict__ out) {
    __shared__ float As[16 * KDIM];      // 24 KB
    __shared__ float Bs[16 * 128];       // 8 KB
    __shared__ float Hs[16 * 132];       // 8.25 KB
    __shared__ float Wds_s[128 * DDIM];  // 32 KB

    const int t = threadIdx.x;
    const int head = blockIdx.y;
    const float* W  = (head == 0) ? Wm  : (head == 1) ? Ws  : Wp;
    const float* Wd = (head == 0) ? Wdm : (head == 1) ? Wds : Wdp;
    const int m0 = blockIdx.x * 16;

    // panel-loader indices (512 float4 per 16x128 panel / 256 thr = 2 each)
    const int pk0 = (t * 2) >> 5;
    const int pc0 = ((t * 2) & 31) * 4;
    const int pk1 = (t * 2 + 1) >> 5;
    const int pc1 = ((t * 2 + 1) & 31) * 4;

    // ---- load A tile (16 x 384, contiguous) + Wd (128 x 64) into smem ----
    {
        const float4* src = reinterpret_cast<const float4*>(
            &g_aggL1[(size_t)m0 * KDIM]);
        float4* dst = reinterpret_cast<float4*>(As);
#pragma unroll
        for (int l = 0; l < 6; l++) dst[t + l * 256] = src[t + l * 256];

        const float4* wsrc = reinterpret_cast<const float4*>(Wd);
        float4* wdst = reinterpret_cast<float4*>(Wds_s);
#pragma unroll
        for (int l = 0; l < 8; l++) wdst[t + l * 256] = wsrc[t + l * 256];
    }

    // prefetch first W panel
    float4 wv0 = *reinterpret_cast<const float4*>(&W[(size_t)pk0 * EDIM + pc0]);
    float4 wv1 = *reinterpret_cast<const float4*>(&W[(size_t)pk1 * EDIM + pc1]);
    __syncthreads();

    // ---- GEMM: thread (ty = t>>5 -> 2 rows, tx = t&31 -> 4 cols) ----
    const int ty = t >> 5;
    const int tx = t & 31;
    float acc[2][4];
#pragma unroll
    for (int i = 0; i < 2; i++)
#pragma unroll
        for (int q = 0; q < 4; q++) acc[i][q] = 0.f;

    for (int k0 = 0; k0 < KDIM; k0 += 16) {
        *reinterpret_cast<float4*>(&Bs[pk0 * 128 + pc0]) = wv0;
        *reinterpret_cast<float4*>(&Bs[pk1 * 128 + pc1]) = wv1;
        __syncthreads();
        if (k0 + 16 < KDIM) {
            wv0 = *reinterpret_cast<const float4*>(
                &W[(size_t)(k0 + 16 + pk0) * EDIM + pc0]);
            wv1 = *reinterpret_cast<const float4*>(
                &W[(size_t)(k0 + 16 + pk1) * EDIM + pc1]);
        }
#pragma unroll
        for (int k = 0; k < 16; k++) {
            float4 b = *reinterpret_cast<const float4*>(&Bs[k * 128 + tx * 4]);
            float a0 = As[(ty * 2) * KDIM + k0 + k];
            float a1 = As[(ty * 2 + 1) * KDIM + k0 + k];
            acc[0][0] += a0 * b.x; acc[0][1] += a0 * b.y;
            acc[0][2] += a0 * b.z; acc[0][3] += a0 * b.w;
            acc[1][0] += a1 * b.x; acc[1][1] += a1 * b.y;
            acc[1][2] += a1 * b.z; acc[1][3] += a1 * b.w;
        }
        __syncthreads();
    }

#pragma unroll
    for (int i = 0; i < 2; i++) {
        float4 o;
        o.x = sigmoidf_stable(acc[i][0]);
        o.y = sigmoidf_stable(acc[i][1]);
        o.z = sigmoidf_stable(acc[i][2]);
        o.w = sigmoidf_stable(acc[i][3]);
        *reinterpret_cast<float4*>(&Hs[(ty * 2 + i) * 132 + tx * 4]) = o;
    }
    __syncthreads();

    // ---- projection: z[16][64] = Hs[16][128] @ Wd[128][64] ----
#pragma unroll
    for (int pass = 0; pass < 4; pass++) {
        int r = pass * 4 + (t >> 6);        // 0..15
        int c = t & 63;
        float s = 0.f;
#pragma unroll
        for (int k = 0; k < 128; k++) {
            s += Hs[r * 132 + k] * Wds_s[k * DDIM + c];
        }
        int R = m0 + r;
        int set = R >> 8, i = R & 255;
        out[((size_t)(set * 3 + head) * BATCH + i) * DDIM + c] = s;
    }
}

// ---------------------------------------------------------------------------
// Host-side JAX threefry reproduction (partitionable mode)
// ---------------------------------------------------------------------------
namespace tfry {

static inline uint32_t rotl32(uint32_t x, int d) { return (x << d) | (x >> (32 - d)); }

struct Key { uint32_t a, b; };

static Key threefry2x32(Key k, uint32_t x0, uint32_t x1) {
    uint32_t ks0 = k.a, ks1 = k.b, ks2 = k.a ^ k.b ^ 0x1BD11BDAu;
    x0 += ks0; x1 += ks1;
    static const int R0[4] = {13, 15, 26, 6};
    static const int R1[4] = {17, 29, 16, 24};
    auto rounds4 = [&](const int* R) {
        for (int i = 0; i < 4; i++) { x0 += x1; x1 = rotl32(x1, R[i]); x1 ^= x0; }
    };
    rounds4(R0); x0 += ks1; x1 += ks2 + 1u;
    rounds4(R1); x0 += ks2; x1 += ks0 + 2u;
    rounds4(R0); x0 += ks0; x1 += ks1 + 3u;
    rounds4(R1); x0 += ks1; x1 += ks2 + 4u;
    rounds4(R0); x0 += ks2; x1 += ks0 + 5u;
    return Key{x0, x1};
}

static Key fold(Key k, uint32_t i) { return threefry2x32(k, 0u, i); }

static void perm64_prefix(Key key, int n, int* out) {
    Key subkey = fold(key, 1);
    uint32_t bits[64];
    int idx[64];
    for (int i = 0; i < 64; i++) {
        Key r = threefry2x32(subkey, 0u, (uint32_t)i);
        bits[i] = r.a ^ r.b;
        idx[i] = i;
    }
    std::stable_sort(idx, idx + 64,
                     [&](int x, int y) { return bits[x] < bits[y]; });
    for (int j = 0; j < n; j++) out[j] = idx[j];
}

}  // namespace tfry

// ---------------------------------------------------------------------------
// kernel_launch
// ---------------------------------------------------------------------------
extern "C" void kernel_launch(void* const* d_in, const int* in_sizes, int n_in,
                              void* d_out, int out_size) {
    const int*   nodes1  = (const int*)d_in[0];
    const int*   nodes2  = (const int*)d_in[1];
    const int*   nbr_out = (const int*)d_in[2];
    const int*   nbr_in  = (const int*)d_in[3];
    const float* feat    = (const float*)d_in[4];
    const float* W_in    = (const float*)d_in[5];
    const float* W_mean  = (const float*)d_in[6];
    const float* W_std   = (const float*)d_in[7];
    const float* W_pi    = (const float*)d_in[8];
    const float* Wd_mean = (const float*)d_in[11];
    const float* Wd_std  = (const float*)d_in[12];
    const float* Wd_pi   = (const float*)d_in[13];
    float* out = (float*)d_out;

    cudaFuncSetAttribute(fused_l0s1, cudaFuncAttributeMaxDynamicSharedMemorySize,
                         SMEM_FUSED);

    // --- host threefry: sampling column indices ---
    ColsAll cols;
    tfry::Key root{0u, 42u};
    tfry::Key kset[2] = {tfry::fold(root, 0), tfry::fold(root, 1)};
    for (int set = 0; set < 2; set++) {
        tfry::Key key = kset[set];
        {
            tfry::Key nk = tfry::fold(key, 0);
            tfry::Key p1 = tfry::fold(key, 1);
            tfry::Key p2 = tfry::fold(key, 2);
            tfry::perm64_prefix(p1, NN1, cols.out0[set]);
            tfry::perm64_prefix(p2, NN1, cols.in0[set]);
            key = nk;
        }
        {
            tfry::Key p1 = tfry::fold(key, 1);
            tfry::Key p2 = tfry::fold(key, 2);
            tfry::perm64_prefix(p1, NN0, cols.out1[set]);
            tfry::perm64_prefix(p2, NN0, cols.in1[set]);
        }
    }

    // --- pipeline: 5 launches ---
    comb_b1_prep<<<PREP_BLOCKS + B1_BLOCKS, 256>>>(nodes1, nodes2, nbr_out,
                                                   nbr_in, W_in, cols);        // #1
    build_lvl2<<<(2 * ROWS2 + 255) / 256, 256>>>(nbr_out, nbr_in, cols);       // #2
    fused_l0s1<<<L0_BLOCKS + S1_BLOCKS, 256, SMEM_FUSED>>>(feat, nodes1,
                                                           nodes2, W_in);      // #3
    agg_l1<<<64, 256>>>();                                                     // #4
    head_proj<<<dim3(32, 3), 256>>>(W_mean, W_std, W_pi,
                                    Wd_mean, Wd_std, Wd_pi, out);              // #5
}